// round 14
// baseline (speedup 1.0000x reference)
#include <cuda_runtime.h>
#include <cuda_bf16.h>
#include <cuda_fp16.h>
#include <stdint.h>

#define N_NODES 50000
#define N_EDGES 500000
#define NPG     6250
#define N_GRAPHS 8
#define TOT_EDGES (N_EDGES + N_NODES)
#define NC 10
#define NBLK_SCAN ((N_NODES + 255) / 256)   // 196

// ===================== mma.sync helpers (sm_80+ ISA) ========================
__device__ __forceinline__ uint32_t smem_to_u32(const void* p) {
    uint32_t a;
    asm("{ .reg .u64 t; cvta.to.shared.u64 t, %1; cvt.u32.u64 %0, t; }" : "=r"(a) : "l"(p));
    return a;
}
#define LDSM4(r, addr) \
    asm volatile("ldmatrix.sync.aligned.m8n8.x4.shared.b16 {%0,%1,%2,%3}, [%4];" \
        : "=r"((r)[0]), "=r"((r)[1]), "=r"((r)[2]), "=r"((r)[3]) : "r"(addr))
#define MMA_BF16(d, a, b0v, b1v) \
    asm volatile("mma.sync.aligned.m16n8k16.row.col.f32.bf16.bf16.f32 " \
        "{%0,%1,%2,%3}, {%4,%5,%6,%7}, {%8,%9}, {%0,%1,%2,%3};" \
        : "+f"((d)[0]), "+f"((d)[1]), "+f"((d)[2]), "+f"((d)[3]) \
        : "r"((a)[0]), "r"((a)[1]), "r"((a)[2]), "r"((a)[3]), "r"(b0v), "r"(b1v))

// ---------------- scratch (static __device__, no allocation) ----------------
__device__ __align__(16) __half g_xp1[(size_t)N_NODES * 256];
__device__ __align__(16) float  g_h1 [(size_t)N_NODES * 128];
__device__ __align__(16) __half g_xp2[(size_t)N_NODES * 128];
__device__ __align__(8) float g_als[N_NODES * 2];
__device__ __align__(8) float g_ald[N_NODES * 2];
__device__ int   g_rowptr[N_NODES + 1];
__device__ int   g_cursor[N_NODES];
__device__ __align__(8) int2 g_cole[TOT_EDGES];   // {src, eav bits}
__device__ float g_gsum[N_GRAPHS];
__device__ int   g_gcnt[N_GRAPHS];
__device__ float g_mean[N_GRAPHS];
__device__ float g_ke[4];
__device__ int   g_blkst[NBLK_SCAN];   // lookback: (sum<<2)|state, 0=none 1=agg 2=prefix

// ---------------- init ------------------------------------------------------
__global__ void k_init() {
    int i = blockIdx.x * blockDim.x + threadIdx.x;
    if (i < N_NODES) g_cursor[i] = 1;
    if (i < N_GRAPHS) { g_gsum[i] = 0.f; g_gcnt[i] = 0; }
    if (i < NBLK_SCAN) g_blkst[i] = 0;
}

// ---------------- edge pass: per-graph attr stats + in-degree hist ----------
__global__ void k_edge_pass1(const int* __restrict__ src, const int* __restrict__ dst,
                             const float* __restrict__ ea) {
    __shared__ float ss[N_GRAPHS];
    __shared__ int   sc[N_GRAPHS];
    if (threadIdx.x < N_GRAPHS) { ss[threadIdx.x] = 0.f; sc[threadIdx.x] = 0; }
    __syncthreads();
    for (int e = blockIdx.x * blockDim.x + threadIdx.x; e < N_EDGES;
         e += gridDim.x * blockDim.x) {
        int s = src[e];
        int d = dst[e];
        int g = s / NPG;
        atomicAdd(&ss[g], ea[e]);
        atomicAdd(&sc[g], 1);
        atomicAdd(&g_cursor[d], 1);
    }
    __syncthreads();
    if (threadIdx.x < N_GRAPHS) {
        atomicAdd(&g_gsum[threadIdx.x], ss[threadIdx.x]);
        atomicAdd(&g_gcnt[threadIdx.x], sc[threadIdx.x]);
    }
}

// ---------------- decoupled-lookback scan + finalize (single launch) --------
__global__ void __launch_bounds__(256) k_scanLB(const float* __restrict__ We1,
                                                const float* __restrict__ ae1,
                                                const float* __restrict__ We2,
                                                const float* __restrict__ ae2) {
    int b = blockIdx.x, t = threadIdx.x, lane = t & 31, w = t >> 5;
    // part A (block 0 only): edge-attention scalars + per-graph means
    if (b == 0) {
        float v = 0.f;
        if (w == 0)      { for (int c = lane; c < 128; c += 32) v += We1[c]       * ae1[c]; }
        else if (w == 1) { for (int c = lane; c < 128; c += 32) v += We1[128 + c] * ae1[128 + c]; }
        else if (w == 2) { for (int c = lane; c <  64; c += 32) v += We2[c]       * ae2[c]; }
        else if (w == 3) { for (int c = lane; c <  64; c += 32) v += We2[64 + c]  * ae2[64 + c]; }
        #pragma unroll
        for (int off = 16; off; off >>= 1) v += __shfl_xor_sync(0xffffffffu, v, off);
        if (w < 4 && lane == 0) g_ke[w] = v;
        if (w == 4 && lane < N_GRAPHS)
            g_mean[lane] = g_gsum[lane] / (float)g_gcnt[lane];
    }
    // per-block scan of 256 degrees
    int i = b * 256 + t;
    int v = (i < N_NODES) ? g_cursor[i] : 0;
    int x = v;
    #pragma unroll
    for (int o = 1; o < 32; o <<= 1) {
        int y = __shfl_up_sync(0xffffffffu, x, o);
        if (lane >= o) x += y;
    }
    __shared__ int ws[8];
    __shared__ int s_off;
    if (lane == 31) ws[w] = x;
    __syncthreads();
    if (t == 0) {
        int run = 0;
        #pragma unroll
        for (int j = 0; j < 8; j++) { int tmp = ws[j]; ws[j] = run; run += tmp; }
        if (b == 0) {
            __threadfence();
            atomicExch(&g_blkst[0], (run << 2) | 2);
            s_off = 0;
        } else {
            __threadfence();
            atomicExch(&g_blkst[b], (run << 2) | 1);
            // lookback over predecessors
            int acc = 0, j = b - 1;
            while (true) {
                int s = atomicAdd(&g_blkst[j], 0);
                int st = s & 3;
                if (st == 0) continue;
                acc += (s >> 2);
                if (st == 2) break;
                j--;
            }
            __threadfence();
            atomicExch(&g_blkst[b], ((acc + run) << 2) | 2);
            s_off = acc;
        }
    }
    __syncthreads();
    int excl = s_off + ws[w] + x - v;
    if (i < N_NODES) { g_rowptr[i] = excl; g_cursor[i] = excl; }
    if (b == 0 && t == 0) g_rowptr[N_NODES] = TOT_EDGES;
}

// ---------------- CSR fill (+ folded y cast) ----------------------------------
__global__ void k_fill(const int* __restrict__ src, const int* __restrict__ dst,
                       const float* __restrict__ ea,
                       const int* __restrict__ y, float* __restrict__ outy) {
    for (int i = blockIdx.x * blockDim.x + threadIdx.x; i < TOT_EDGES;
         i += gridDim.x * blockDim.x) {
        if (i < N_EDGES) {
            int d = dst[i];
            int p = atomicAdd(&g_cursor[d], 1);
            g_cole[p] = make_int2(src[i], __float_as_int(ea[i]));
        } else {
            int n = i - N_EDGES;
            int p = atomicAdd(&g_cursor[n], 1);
            g_cole[p] = make_int2(n, __float_as_int(g_mean[n / NPG]));
            if (outy) outy[n] = (float)y[n];
        }
    }
}

// ============ split-bf16 mma.sync GEMM + fused attention-logit epilogue ======
static constexpr int MMA_STR  = 80;
static constexpr int MMA_MATB = 128 * MMA_STR;
static constexpr int MMA_BUFB = 4 * MMA_MATB;
static constexpr int MMA_SMEM = 2 * MMA_BUFB + 512 + 512 + 1024 + 1024; // 84992

template <int KDIM, int CH>
__device__ __forceinline__ void cvt_store_chunk(char* smem, int bufoff,
                                                const float4* pfa, const float* pfw,
                                                int tid) {
    #pragma unroll
    for (int i = 0; i < 4; i++) {
        int idx = tid + i * 256;
        int row = idx >> 3, kq = idx & 7;
        float4 v = pfa[i];
        __nv_bfloat162 h0, h1, l0, l1;
        h0.x = __float2bfloat16(v.x); h0.y = __float2bfloat16(v.y);
        h1.x = __float2bfloat16(v.z); h1.y = __float2bfloat16(v.w);
        l0.x = __float2bfloat16(v.x - __bfloat162float(h0.x));
        l0.y = __float2bfloat16(v.y - __bfloat162float(h0.y));
        l1.x = __float2bfloat16(v.z - __bfloat162float(h1.x));
        l1.y = __float2bfloat16(v.w - __bfloat162float(h1.y));
        char* p = smem + bufoff + row * MMA_STR + kq * 8;
        *reinterpret_cast<__nv_bfloat162*>(p)     = h0;
        *reinterpret_cast<__nv_bfloat162*>(p + 4) = h1;
        *reinterpret_cast<__nv_bfloat162*>(p + MMA_MATB)     = l0;
        *reinterpret_cast<__nv_bfloat162*>(p + MMA_MATB + 4) = l1;
    }
    #pragma unroll
    for (int i = 0; i < 8; i++) {
        int idx = tid + i * 256;
        int k2 = idx >> 7, n = idx & 127;
        float w0 = pfw[2 * i], w1 = pfw[2 * i + 1];
        __nv_bfloat162 h, l;
        h.x = __float2bfloat16(w0); h.y = __float2bfloat16(w1);
        l.x = __float2bfloat16(w0 - __bfloat162float(h.x));
        l.y = __float2bfloat16(w1 - __bfloat162float(h.y));
        char* p = smem + bufoff + 2 * MMA_MATB + n * MMA_STR + k2 * 4;
        *reinterpret_cast<__nv_bfloat162*>(p)            = h;
        *reinterpret_cast<__nv_bfloat162*>(p + MMA_MATB) = l;
    }
}

template <int KDIM, int CH>
__global__ void __launch_bounds__(256) k_mma(const float* __restrict__ A,
                                             const float* __restrict__ W,
                                             __half* __restrict__ xp,
                                             const float* __restrict__ asrc,
                                             const float* __restrict__ adst,
                                             int M) {
    extern __shared__ char smem[];
    constexpr int NW  = 2 * CH;
    constexpr int KCH = KDIM / 32;
    constexpr int SAS  = 2 * MMA_BUFB;
    constexpr int SAD  = SAS + 512;
    constexpr int SALS = SAD + 512;
    constexpr int SALD = SALS + 1024;

    const int tid = threadIdx.x;
    const int wid = tid >> 5, lane = tid & 31;
    const int wm = wid & 3, wn = wid >> 2;
    const int brow = blockIdx.y * 128;
    const int bcol = blockIdx.x * 128;
    const uint32_t sb = smem_to_u32(smem);

    float* s_as  = reinterpret_cast<float*>(smem + SAS);
    float* s_ad  = reinterpret_cast<float*>(smem + SAD);
    float* s_als = reinterpret_cast<float*>(smem + SALS);
    float* s_ald = reinterpret_cast<float*>(smem + SALD);
    if (tid < 128) { s_as[tid] = asrc[bcol + tid]; s_ad[tid] = adst[bcol + tid]; }
    s_als[tid] = 0.f;
    s_ald[tid] = 0.f;

    const uint32_t aoff = (uint32_t)((lane & 15) * MMA_STR + (lane >> 4) * 16);
    const uint32_t boff = (uint32_t)(((lane & 7) + ((lane >> 4) & 1) * 8) * MMA_STR
                                     + ((lane >> 3) & 1) * 16);

    float4 pfa[4];
    float  pfw[16];
    #pragma unroll
    for (int i = 0; i < 4; i++) {
        int idx = tid + i * 256;
        int row = idx >> 3, kq = idx & 7;
        int gr = brow + row;
        pfa[i] = (gr < M) ? *reinterpret_cast<const float4*>(A + (size_t)gr * KDIM + kq * 4)
                          : make_float4(0.f, 0.f, 0.f, 0.f);
    }
    #pragma unroll
    for (int i = 0; i < 8; i++) {
        int idx = tid + i * 256;
        int k = (idx >> 7) * 2, n = idx & 127;
        pfw[2 * i]     = W[(size_t)k * NW + bcol + n];
        pfw[2 * i + 1] = W[(size_t)(k + 1) * NW + bcol + n];
    }
    cvt_store_chunk<KDIM, CH>(smem, 0, pfa, pfw, tid);
    __syncthreads();

    float acc[2][8][4];
    #pragma unroll
    for (int a = 0; a < 2; a++)
        #pragma unroll
        for (int b = 0; b < 8; b++)
            #pragma unroll
            for (int c = 0; c < 4; c++) acc[a][b][c] = 0.f;

    int buf = 0;
    for (int kc = 0; kc < KCH; kc++) {
        if (kc + 1 < KCH) {
            const int kb = (kc + 1) * 32;
            #pragma unroll
            for (int i = 0; i < 4; i++) {
                int idx = tid + i * 256;
                int row = idx >> 3, kq = idx & 7;
                int gr = brow + row;
                pfa[i] = (gr < M)
                    ? *reinterpret_cast<const float4*>(A + (size_t)gr * KDIM + kb + kq * 4)
                    : make_float4(0.f, 0.f, 0.f, 0.f);
            }
            #pragma unroll
            for (int i = 0; i < 8; i++) {
                int idx = tid + i * 256;
                int k = kb + (idx >> 7) * 2, n = idx & 127;
                pfw[2 * i]     = W[(size_t)k * NW + bcol + n];
                pfw[2 * i + 1] = W[(size_t)(k + 1) * NW + bcol + n];
            }
        }
        const uint32_t baseA = sb + buf * MMA_BUFB;
        const uint32_t baseB = baseA + 2 * MMA_MATB;
        #pragma unroll
        for (int ks = 0; ks < 2; ks++) {
            uint32_t ah[2][4], al[2][4], bh[4][4], bl[4][4];
            #pragma unroll
            for (int mf = 0; mf < 2; mf++) {
                uint32_t ad = baseA + (uint32_t)((wm * 32 + mf * 16) * MMA_STR) + ks * 32 + aoff;
                LDSM4(ah[mf], ad);
                LDSM4(al[mf], ad + MMA_MATB);
            }
            #pragma unroll
            for (int np = 0; np < 4; np++) {
                uint32_t bd = baseB + (uint32_t)((wn * 64 + np * 16) * MMA_STR) + ks * 32 + boff;
                LDSM4(bh[np], bd);
                LDSM4(bl[np], bd + MMA_MATB);
            }
            #pragma unroll
            for (int mf = 0; mf < 2; mf++)
                #pragma unroll
                for (int np = 0; np < 4; np++)
                    #pragma unroll
                    for (int hh = 0; hh < 2; hh++) {
                        int nf = np * 2 + hh;
                        MMA_BF16(acc[mf][nf], ah[mf], bh[np][2 * hh], bh[np][2 * hh + 1]);
                        MMA_BF16(acc[mf][nf], al[mf], bh[np][2 * hh], bh[np][2 * hh + 1]);
                        MMA_BF16(acc[mf][nf], ah[mf], bl[np][2 * hh], bl[np][2 * hh + 1]);
                    }
        }
        if (kc + 1 < KCH) {
            cvt_store_chunk<KDIM, CH>(smem, (buf ^ 1) * MMA_BUFB, pfa, pfw, tid);
            __syncthreads();
            buf ^= 1;
        }
    }

    // ---- epilogue: write xp (fp16) + fused attention logits (fp32) ----
    #pragma unroll
    for (int mf = 0; mf < 2; mf++)
        #pragma unroll
        for (int r = 0; r < 2; r++) {
            int row_local = wm * 32 + mf * 16 + (lane >> 2) + r * 8;
            int m = brow + row_local;
            float als = 0.f, ald = 0.f;
            #pragma unroll
            for (int nf = 0; nf < 8; nf++) {
                float c0 = acc[mf][nf][r * 2 + 0], c1 = acc[mf][nf][r * 2 + 1];
                int j = wn * 64 + nf * 8 + (lane & 3) * 2;
                als += c0 * s_as[j] + c1 * s_as[j + 1];
                ald += c0 * s_ad[j] + c1 * s_ad[j + 1];
                if (m < M) {
                    int ncol = bcol + j;
                    int head = ncol / CH, c = ncol % CH;
                    *reinterpret_cast<__half2*>(xp + ((size_t)m * 2 + head) * CH + c) =
                        __floats2half2_rn(c0, c1);
                }
            }
            als += __shfl_xor_sync(0xffffffffu, als, 1);
            als += __shfl_xor_sync(0xffffffffu, als, 2);
            ald += __shfl_xor_sync(0xffffffffu, ald, 1);
            ald += __shfl_xor_sync(0xffffffffu, ald, 2);
            if ((lane & 3) == 0) {
                int sidx = (CH == 64 ? wn * 128 : 0) + row_local;
                atomicAdd(&s_als[sidx], als);
                atomicAdd(&s_ald[sidx], ald);
            }
        }
    __syncthreads();
    if (CH == 128) {
        if (tid < 128) {
            int m = brow + tid;
            if (m < M) {
                g_als[2 * m + blockIdx.x] = s_als[tid];
                g_ald[2 * m + blockIdx.x] = s_ald[tid];
            }
        }
    } else {
        int h = tid >> 7, t = tid & 127;
        int m = brow + t;
        if (m < M) {
            g_als[2 * m + h] = s_als[tid];
            g_ald[2 * m + h] = s_ald[tid];
        }
    }
}

// ---------------- warp-per-dst online-softmax aggregation (R13 layout) -------
template <int C>
__device__ __forceinline__ void ld_row(const __half* row, float* v0, float* v1) {
    constexpr int V = C / 32;
    if constexpr (V == 4) {
        uint2 u0 = *reinterpret_cast<const uint2*>(row);
        uint2 u1 = *reinterpret_cast<const uint2*>(row + C);
        float2 a = __half22float2(*reinterpret_cast<__half2*>(&u0.x));
        float2 b = __half22float2(*reinterpret_cast<__half2*>(&u0.y));
        v0[0] = a.x; v0[1] = a.y; v0[2] = b.x; v0[3] = b.y;
        a = __half22float2(*reinterpret_cast<__half2*>(&u1.x));
        b = __half22float2(*reinterpret_cast<__half2*>(&u1.y));
        v1[0] = a.x; v1[1] = a.y; v1[2] = b.x; v1[3] = b.y;
    } else {
        float2 a = __half22float2(*reinterpret_cast<const __half2*>(row));
        float2 b = __half22float2(*reinterpret_cast<const __half2*>(row + C));
        v0[0] = a.x; v0[1] = a.y;
        v1[0] = b.x; v1[1] = b.y;
    }
}

template <int C, bool RELU, bool CLS>
__global__ void k_agg(const __half* __restrict__ xp, const float* __restrict__ bias,
                      float* __restrict__ out, int keoff,
                      const float* __restrict__ Wc, const float* __restrict__ bc) {
    int warp = (blockIdx.x * blockDim.x + threadIdx.x) >> 5;
    int lane = threadIdx.x & 31;
    if (warp >= N_NODES) return;
    constexpr int V = C / 32;
    float acc0[V], acc1[V];
    #pragma unroll
    for (int j = 0; j < V; j++) { acc0[j] = 0.f; acc1[j] = 0.f; }
    float m0 = -1e30f, m1 = -1e30f, d0 = 0.f, d1 = 0.f;
    float ad0 = g_ald[2 * warp], ad1 = g_ald[2 * warp + 1];
    float ke0 = g_ke[keoff], ke1 = g_ke[keoff + 1];
    int p0 = g_rowptr[warp], p1 = g_rowptr[warp + 1];
    int c0 = lane * V;

    int p = p0;
    for (; p + 3 < p1; p += 4) {
        int2 ce[4];
        ce[0] = g_cole[p];     ce[1] = g_cole[p + 1];
        ce[2] = g_cole[p + 2]; ce[3] = g_cole[p + 3];
        float v0[4][V], v1[4][V];
        #pragma unroll
        for (int e = 0; e < 4; e++)
            ld_row<C>(xp + (size_t)ce[e].x * 2 * C + c0, v0[e], v1[e]);
        float a0[4], a1[4];
        #pragma unroll
        for (int e = 0; e < 4; e++) {
            float ea = __int_as_float(ce[e].y);
            float t0 = g_als[2 * ce[e].x]     + ad0 + ea * ke0;
            float t1 = g_als[2 * ce[e].x + 1] + ad1 + ea * ke1;
            a0[e] = t0 > 0.f ? t0 : 0.2f * t0;
            a1[e] = t1 > 0.f ? t1 : 0.2f * t1;
        }
        float nm0 = fmaxf(fmaxf(m0, fmaxf(a0[0], a0[1])), fmaxf(a0[2], a0[3]));
        float nm1 = fmaxf(fmaxf(m1, fmaxf(a1[0], a1[1])), fmaxf(a1[2], a1[3]));
        float sc0 = __expf(m0 - nm0), sc1 = __expf(m1 - nm1);
        float w0[4], w1[4];
        #pragma unroll
        for (int e = 0; e < 4; e++) {
            w0[e] = __expf(a0[e] - nm0);
            w1[e] = __expf(a1[e] - nm1);
        }
        d0 = d0 * sc0 + (w0[0] + w0[1]) + (w0[2] + w0[3]);
        d1 = d1 * sc1 + (w1[0] + w1[1]) + (w1[2] + w1[3]);
        m0 = nm0;  m1 = nm1;
        #pragma unroll
        for (int j = 0; j < V; j++) {
            float s0 = fmaf(w0[0], v0[0][j], w0[1] * v0[1][j]);
            s0 = fmaf(w0[2], v0[2][j], fmaf(w0[3], v0[3][j], s0));
            acc0[j] = fmaf(acc0[j], sc0, s0);
            float s1 = fmaf(w1[0], v1[0][j], w1[1] * v1[1][j]);
            s1 = fmaf(w1[2], v1[2][j], fmaf(w1[3], v1[3][j], s1));
            acc1[j] = fmaf(acc1[j], sc1, s1);
        }
    }
    for (; p < p1; p++) {
        int2 ce = g_cole[p];
        int s = ce.x;
        float ea = __int_as_float(ce.y);
        float v0[V], v1[V];
        ld_row<C>(xp + (size_t)s * 2 * C + c0, v0, v1);
        float a0 = g_als[2 * s]     + ad0 + ea * ke0;
        float a1 = g_als[2 * s + 1] + ad1 + ea * ke1;
        a0 = a0 > 0.f ? a0 : 0.2f * a0;
        a1 = a1 > 0.f ? a1 : 0.2f * a1;
        float nm0 = fmaxf(m0, a0), nm1 = fmaxf(m1, a1);
        float sc0 = __expf(m0 - nm0), sc1 = __expf(m1 - nm1);
        float w0  = __expf(a0 - nm0), w1  = __expf(a1 - nm1);
        d0 = d0 * sc0 + w0;  d1 = d1 * sc1 + w1;
        m0 = nm0;  m1 = nm1;
        #pragma unroll
        for (int j = 0; j < V; j++) {
            acc0[j] = fmaf(acc0[j], sc0, w0 * v0[j]);
            acc1[j] = fmaf(acc1[j], sc1, w1 * v1[j]);
        }
    }

    float r0 = 1.f / (d0 + 1e-16f), r1 = 1.f / (d1 + 1e-16f);
    float res[V];
    #pragma unroll
    for (int j = 0; j < V; j++) {
        float vv = 0.5f * (acc0[j] * r0 + acc1[j] * r1) + bias[c0 + j];
        if (RELU) vv = fmaxf(vv, 0.f);
        res[j] = vv;
    }
    if constexpr (!CLS) {
        if constexpr (V == 4)
            *reinterpret_cast<float4*>(&out[(size_t)warp * C + c0]) =
                make_float4(res[0], res[1], res[2], res[3]);
        else
            *reinterpret_cast<float2*>(&out[(size_t)warp * C + c0]) =
                make_float2(res[0], res[1]);
    } else {
        float part[NC];
        #pragma unroll
        for (int c = 0; c < NC; c++) {
            float s = 0.f;
            #pragma unroll
            for (int j = 0; j < V; j++)
                s = fmaf(res[j], __ldg(&Wc[(c0 + j) * NC + c]), s);
            part[c] = s;
        }
        #pragma unroll
        for (int off = 16; off; off >>= 1)
            #pragma unroll
            for (int c = 0; c < NC; c++)
                part[c] += __shfl_xor_sync(0xffffffffu, part[c], off);
        if (lane < NC)
            out[(size_t)warp * NC + lane] = part[lane] + __ldg(&bc[lane]);
    }
}

// ---------------- launch ------------------------------------------------------
static void* sym(const void* s) { void* p = nullptr; cudaGetSymbolAddress(&p, s); return p; }

extern "C" void kernel_launch(void* const* d_in, const int* in_sizes, int n_in,
                              void* d_out, int out_size) {
    const float* x    = (const float*)d_in[0];
    const int*   ei   = (const int*)  d_in[1];
    const float* ea   = (const float*)d_in[2];
    const int*   y    = (const int*)  d_in[4];
    const float* W1   = (const float*)d_in[5];
    const float* as1  = (const float*)d_in[6];
    const float* ad1  = (const float*)d_in[7];
    const float* We1  = (const float*)d_in[8];
    const float* ae1  = (const float*)d_in[9];
    const float* b1   = (const float*)d_in[10];
    const float* W2   = (const float*)d_in[11];
    const float* as2  = (const float*)d_in[12];
    const float* ad2  = (const float*)d_in[13];
    const float* We2  = (const float*)d_in[14];
    const float* ae2  = (const float*)d_in[15];
    const float* b2   = (const float*)d_in[16];
    const float* Wc   = (const float*)d_in[17];
    const float* bc   = (const float*)d_in[18];
    float* out = (float*)d_out;
    const int* src = ei;
    const int* dst = ei + N_EDGES;

    __half* xp1 = (__half*)sym(g_xp1);
    float*  h1  = (float*) sym(g_h1);
    __half* xp2 = (__half*)sym(g_xp2);

    static cudaStream_t s2 = nullptr;
    static cudaEvent_t evFork = nullptr, evCSR = nullptr;
    if (!s2) {
        cudaStreamCreateWithFlags(&s2, cudaStreamNonBlocking);
        cudaEventCreateWithFlags(&evFork, cudaEventDisableTiming);
        cudaEventCreateWithFlags(&evCSR, cudaEventDisableTiming);
    }

    cudaFuncSetAttribute(k_mma<256, 128>,
                         cudaFuncAttributeMaxDynamicSharedMemorySize, MMA_SMEM);
    cudaFuncSetAttribute(k_mma<128, 64>,
                         cudaFuncAttributeMaxDynamicSharedMemorySize, MMA_SMEM);

    const int MB = (N_NODES + 127) / 128;                // 391
    const int AGG_GRID = (N_NODES * 32 + 255) / 256;     // 6250

    float* outy = (out_size >= N_NODES * NC + N_NODES)
                      ? out + (size_t)N_NODES * NC : nullptr;

    // ---- fork: compact CSR chain on s2 concurrent with layer-1 GEMM ----
    cudaEventRecord(evFork, 0);
    cudaStreamWaitEvent(s2, evFork, 0);

    k_init<<<(N_NODES + 255) / 256, 256, 0, s2>>>();
    k_edge_pass1<<<512, 256, 0, s2>>>(src, dst, ea);
    k_scanLB<<<NBLK_SCAN, 256, 0, s2>>>(We1, ae1, We2, ae2);
    k_fill<<<1024, 256, 0, s2>>>(src, dst, ea, y, outy);
    cudaEventRecord(evCSR, s2);

    // main: layer-1 fused GEMM concurrent with CSR build
    k_mma<256, 128><<<dim3(2, MB), 256, MMA_SMEM>>>(x, W1, xp1, as1, ad1, N_NODES);
    cudaStreamWaitEvent(0, evCSR, 0);

    // layer 1 aggregation
    k_agg<128, true, false><<<AGG_GRID, 256>>>(xp1, b1, h1, 0, nullptr, nullptr);

    // layer 2 + fused classifier
    k_mma<128, 64><<<dim3(1, MB), 256, MMA_SMEM>>>(h1, W2, xp2, as2, ad2, N_NODES);
    k_agg<64, false, true><<<AGG_GRID, 256>>>(xp2, b2, out, 2, Wc, bc);
}

// round 15
// speedup vs baseline: 1.0175x; 1.0175x over previous
#include <cuda_runtime.h>
#include <cuda_bf16.h>
#include <cuda_fp16.h>
#include <stdint.h>

#define N_NODES 50000
#define N_EDGES 500000
#define NPG     6250
#define N_GRAPHS 8
#define TOT_EDGES (N_EDGES + N_NODES)
#define NC 10
#define NBLK_SCAN ((N_NODES + 255) / 256)   // 196

// ===================== mma.sync helpers (sm_80+ ISA) ========================
__device__ __forceinline__ uint32_t smem_to_u32(const void* p) {
    uint32_t a;
    asm("{ .reg .u64 t; cvta.to.shared.u64 t, %1; cvt.u32.u64 %0, t; }" : "=r"(a) : "l"(p));
    return a;
}
#define LDSM4(r, addr) \
    asm volatile("ldmatrix.sync.aligned.m8n8.x4.shared.b16 {%0,%1,%2,%3}, [%4];" \
        : "=r"((r)[0]), "=r"((r)[1]), "=r"((r)[2]), "=r"((r)[3]) : "r"(addr))
#define MMA_BF16(d, a, b0v, b1v) \
    asm volatile("mma.sync.aligned.m16n8k16.row.col.f32.bf16.bf16.f32 " \
        "{%0,%1,%2,%3}, {%4,%5,%6,%7}, {%8,%9}, {%0,%1,%2,%3};" \
        : "+f"((d)[0]), "+f"((d)[1]), "+f"((d)[2]), "+f"((d)[3]) \
        : "r"((a)[0]), "r"((a)[1]), "r"((a)[2]), "r"((a)[3]), "r"(b0v), "r"(b1v))

// ---------------- scratch (static __device__, no allocation) ----------------
__device__ __align__(16) __half g_xp1[(size_t)N_NODES * 256];
__device__ __align__(16) __half g_h1 [(size_t)N_NODES * 128];   // fp16 now
__device__ __align__(16) __half g_xp2[(size_t)N_NODES * 128];
__device__ __align__(8) float g_als[N_NODES * 2];
__device__ __align__(8) float g_ald[N_NODES * 2];
__device__ int   g_rowptr[N_NODES + 1];
__device__ int   g_cursor[N_NODES];
__device__ __align__(8) int2 g_cole[TOT_EDGES];   // {src, eav bits}
__device__ float g_gsum[N_GRAPHS];
__device__ int   g_gcnt[N_GRAPHS];
__device__ float g_mean[N_GRAPHS];
__device__ float g_ke[4];
__device__ int   g_bsum[NBLK_SCAN];

// ---------------- init ------------------------------------------------------
__global__ void k_init() {
    int i = blockIdx.x * blockDim.x + threadIdx.x;
    if (i < N_NODES) g_cursor[i] = 1;
    if (i < N_GRAPHS) { g_gsum[i] = 0.f; g_gcnt[i] = 0; }
}

// ---------------- edge pass: per-graph attr stats + in-degree hist ----------
__global__ void k_edge_pass1(const int* __restrict__ src, const int* __restrict__ dst,
                             const float* __restrict__ ea) {
    __shared__ float ss[N_GRAPHS];
    __shared__ int   sc[N_GRAPHS];
    if (threadIdx.x < N_GRAPHS) { ss[threadIdx.x] = 0.f; sc[threadIdx.x] = 0; }
    __syncthreads();
    for (int e = blockIdx.x * blockDim.x + threadIdx.x; e < N_EDGES;
         e += gridDim.x * blockDim.x) {
        int s = src[e];
        int d = dst[e];
        int g = s / NPG;
        atomicAdd(&ss[g], ea[e]);
        atomicAdd(&sc[g], 1);
        atomicAdd(&g_cursor[d], 1);
    }
    __syncthreads();
    if (threadIdx.x < N_GRAPHS) {
        atomicAdd(&g_gsum[threadIdx.x], ss[threadIdx.x]);
        atomicAdd(&g_gcnt[threadIdx.x], sc[threadIdx.x]);
    }
}

// ---------------- scan stage 1 -----------------------------------------------
__global__ void k_scan1() {
    int t = threadIdx.x;
    int i = blockIdx.x * 256 + t;
    int v = (i < N_NODES) ? g_cursor[i] : 0;
    int lane = t & 31, w = t >> 5;
    int x = v;
    #pragma unroll
    for (int o = 1; o < 32; o <<= 1) {
        int y = __shfl_up_sync(0xffffffffu, x, o);
        if (lane >= o) x += y;
    }
    __shared__ int ws[8];
    if (lane == 31) ws[w] = x;
    __syncthreads();
    if (t == 0) {
        int run = 0;
        #pragma unroll
        for (int j = 0; j < 8; j++) { int tmp = ws[j]; ws[j] = run; run += tmp; }
        g_bsum[blockIdx.x] = run;
    }
    __syncthreads();
    int excl = x - v + ws[w];
    if (i < N_NODES) g_rowptr[i] = excl;
}

// ---------------- scan stage 2 + finalize ------------------------------------
__global__ void k_scan2f(const float* __restrict__ We1, const float* __restrict__ ae1,
                         const float* __restrict__ We2, const float* __restrict__ ae2) {
    int t = threadIdx.x, w = t >> 5, lane = t & 31;
    {
        float v = 0.f;
        if (w == 0)      { for (int c = lane; c < 128; c += 32) v += We1[c]       * ae1[c]; }
        else if (w == 1) { for (int c = lane; c < 128; c += 32) v += We1[128 + c] * ae1[128 + c]; }
        else if (w == 2) { for (int c = lane; c <  64; c += 32) v += We2[c]       * ae2[c]; }
        else if (w == 3) { for (int c = lane; c <  64; c += 32) v += We2[64 + c]  * ae2[64 + c]; }
        #pragma unroll
        for (int off = 16; off; off >>= 1) v += __shfl_xor_sync(0xffffffffu, v, off);
        if (w < 4 && lane == 0) g_ke[w] = v;
        if (w == 4 && lane < N_GRAPHS)
            g_mean[lane] = g_gsum[lane] / (float)g_gcnt[lane];
    }
    int v = (t < NBLK_SCAN) ? g_bsum[t] : 0;
    int x = v;
    #pragma unroll
    for (int o = 1; o < 32; o <<= 1) {
        int y = __shfl_up_sync(0xffffffffu, x, o);
        if (lane >= o) x += y;
    }
    __shared__ int ws[8];
    if (lane == 31) ws[w] = x;
    __syncthreads();
    if (t == 0) {
        int run = 0;
        #pragma unroll
        for (int j = 0; j < 8; j++) { int tmp = ws[j]; ws[j] = run; run += tmp; }
        g_rowptr[N_NODES] = run;
    }
    __syncthreads();
    int excl = x - v + ws[w];
    if (t < NBLK_SCAN) g_bsum[t] = excl;
}

__global__ void k_scan3() {
    int i = blockIdx.x * 256 + threadIdx.x;
    if (i < N_NODES) {
        int r = g_rowptr[i] + g_bsum[blockIdx.x];
        g_rowptr[i] = r;
        g_cursor[i] = r;
    }
}

// ---------------- CSR fill (+ folded y cast) ----------------------------------
__global__ void k_fill(const int* __restrict__ src, const int* __restrict__ dst,
                       const float* __restrict__ ea,
                       const int* __restrict__ y, float* __restrict__ outy) {
    for (int i = blockIdx.x * blockDim.x + threadIdx.x; i < TOT_EDGES;
         i += gridDim.x * blockDim.x) {
        if (i < N_EDGES) {
            int d = dst[i];
            int p = atomicAdd(&g_cursor[d], 1);
            g_cole[p] = make_int2(src[i], __float_as_int(ea[i]));
        } else {
            int n = i - N_EDGES;
            int p = atomicAdd(&g_cursor[n], 1);
            g_cole[p] = make_int2(n, __float_as_int(g_mean[n / NPG]));
            if (outy) outy[n] = (float)y[n];
        }
    }
}

// ============ split-bf16 mma.sync GEMM + fused attention-logit epilogue ======
static constexpr int MMA_STR  = 80;
static constexpr int MMA_MATB = 128 * MMA_STR;
static constexpr int MMA_BUFB = 4 * MMA_MATB;
static constexpr int MMA_SMEM = 2 * MMA_BUFB + 512 + 512 + 1024 + 1024; // 84992

template <int KDIM, int CH>
__device__ __forceinline__ void cvt_store_chunk(char* smem, int bufoff,
                                                const float4* pfa, const float* pfw,
                                                int tid) {
    #pragma unroll
    for (int i = 0; i < 4; i++) {
        int idx = tid + i * 256;
        int row = idx >> 3, kq = idx & 7;
        float4 v = pfa[i];
        __nv_bfloat162 h0, h1, l0, l1;
        h0.x = __float2bfloat16(v.x); h0.y = __float2bfloat16(v.y);
        h1.x = __float2bfloat16(v.z); h1.y = __float2bfloat16(v.w);
        l0.x = __float2bfloat16(v.x - __bfloat162float(h0.x));
        l0.y = __float2bfloat16(v.y - __bfloat162float(h0.y));
        l1.x = __float2bfloat16(v.z - __bfloat162float(h1.x));
        l1.y = __float2bfloat16(v.w - __bfloat162float(h1.y));
        char* p = smem + bufoff + row * MMA_STR + kq * 8;
        *reinterpret_cast<__nv_bfloat162*>(p)     = h0;
        *reinterpret_cast<__nv_bfloat162*>(p + 4) = h1;
        *reinterpret_cast<__nv_bfloat162*>(p + MMA_MATB)     = l0;
        *reinterpret_cast<__nv_bfloat162*>(p + MMA_MATB + 4) = l1;
    }
    #pragma unroll
    for (int i = 0; i < 8; i++) {
        int idx = tid + i * 256;
        int k2 = idx >> 7, n = idx & 127;
        float w0 = pfw[2 * i], w1 = pfw[2 * i + 1];
        __nv_bfloat162 h, l;
        h.x = __float2bfloat16(w0); h.y = __float2bfloat16(w1);
        l.x = __float2bfloat16(w0 - __bfloat162float(h.x));
        l.y = __float2bfloat16(w1 - __bfloat162float(h.y));
        char* p = smem + bufoff + 2 * MMA_MATB + n * MMA_STR + k2 * 4;
        *reinterpret_cast<__nv_bfloat162*>(p)            = h;
        *reinterpret_cast<__nv_bfloat162*>(p + MMA_MATB) = l;
    }
}

// A-tile loader: fp32 (float4) or fp16 (uint2 of 4 halves), same logical slot.
template <typename AT, int KDIM>
__device__ __forceinline__ float4 load_a4(const AT* A, int gr, int k0, bool valid);
template <>
__device__ __forceinline__ float4 load_a4<float, 256>(const float* A, int gr, int k0, bool valid) {
    return valid ? *reinterpret_cast<const float4*>(A + (size_t)gr * 256 + k0)
                 : make_float4(0.f, 0.f, 0.f, 0.f);
}
template <>
__device__ __forceinline__ float4 load_a4<__half, 128>(const __half* A, int gr, int k0, bool valid) {
    if (!valid) return make_float4(0.f, 0.f, 0.f, 0.f);
    uint2 u = *reinterpret_cast<const uint2*>(A + (size_t)gr * 128 + k0);
    float2 a = __half22float2(*reinterpret_cast<__half2*>(&u.x));
    float2 b = __half22float2(*reinterpret_cast<__half2*>(&u.y));
    return make_float4(a.x, a.y, b.x, b.y);
}

template <int KDIM, int CH, typename AT>
__global__ void __launch_bounds__(256) k_mma(const AT* __restrict__ A,
                                             const float* __restrict__ W,
                                             __half* __restrict__ xp,
                                             const float* __restrict__ asrc,
                                             const float* __restrict__ adst,
                                             int M) {
    extern __shared__ char smem[];
    constexpr int NW  = 2 * CH;
    constexpr int KCH = KDIM / 32;
    constexpr int SAS  = 2 * MMA_BUFB;
    constexpr int SAD  = SAS + 512;
    constexpr int SALS = SAD + 512;
    constexpr int SALD = SALS + 1024;

    const int tid = threadIdx.x;
    const int wid = tid >> 5, lane = tid & 31;
    const int wm = wid & 3, wn = wid >> 2;
    const int brow = blockIdx.y * 128;
    const int bcol = blockIdx.x * 128;
    const uint32_t sb = smem_to_u32(smem);

    float* s_as  = reinterpret_cast<float*>(smem + SAS);
    float* s_ad  = reinterpret_cast<float*>(smem + SAD);
    float* s_als = reinterpret_cast<float*>(smem + SALS);
    float* s_ald = reinterpret_cast<float*>(smem + SALD);
    if (tid < 128) { s_as[tid] = asrc[bcol + tid]; s_ad[tid] = adst[bcol + tid]; }
    s_als[tid] = 0.f;
    s_ald[tid] = 0.f;

    const uint32_t aoff = (uint32_t)((lane & 15) * MMA_STR + (lane >> 4) * 16);
    const uint32_t boff = (uint32_t)(((lane & 7) + ((lane >> 4) & 1) * 8) * MMA_STR
                                     + ((lane >> 3) & 1) * 16);

    float4 pfa[4];
    float  pfw[16];
    #pragma unroll
    for (int i = 0; i < 4; i++) {
        int idx = tid + i * 256;
        int row = idx >> 3, kq = idx & 7;
        int gr = brow + row;
        pfa[i] = load_a4<AT, KDIM>(A, gr, kq * 4, gr < M);
    }
    #pragma unroll
    for (int i = 0; i < 8; i++) {
        int idx = tid + i * 256;
        int k = (idx >> 7) * 2, n = idx & 127;
        pfw[2 * i]     = W[(size_t)k * NW + bcol + n];
        pfw[2 * i + 1] = W[(size_t)(k + 1) * NW + bcol + n];
    }
    cvt_store_chunk<KDIM, CH>(smem, 0, pfa, pfw, tid);
    __syncthreads();

    float acc[2][8][4];
    #pragma unroll
    for (int a = 0; a < 2; a++)
        #pragma unroll
        for (int b = 0; b < 8; b++)
            #pragma unroll
            for (int c = 0; c < 4; c++) acc[a][b][c] = 0.f;

    int buf = 0;
    for (int kc = 0; kc < KCH; kc++) {
        if (kc + 1 < KCH) {
            const int kb = (kc + 1) * 32;
            #pragma unroll
            for (int i = 0; i < 4; i++) {
                int idx = tid + i * 256;
                int row = idx >> 3, kq = idx & 7;
                int gr = brow + row;
                pfa[i] = load_a4<AT, KDIM>(A, gr, kb + kq * 4, gr < M);
            }
            #pragma unroll
            for (int i = 0; i < 8; i++) {
                int idx = tid + i * 256;
                int k = kb + (idx >> 7) * 2, n = idx & 127;
                pfw[2 * i]     = W[(size_t)k * NW + bcol + n];
                pfw[2 * i + 1] = W[(size_t)(k + 1) * NW + bcol + n];
            }
        }
        const uint32_t baseA = sb + buf * MMA_BUFB;
        const uint32_t baseB = baseA + 2 * MMA_MATB;
        #pragma unroll
        for (int ks = 0; ks < 2; ks++) {
            uint32_t ah[2][4], al[2][4], bh[4][4], bl[4][4];
            #pragma unroll
            for (int mf = 0; mf < 2; mf++) {
                uint32_t ad = baseA + (uint32_t)((wm * 32 + mf * 16) * MMA_STR) + ks * 32 + aoff;
                LDSM4(ah[mf], ad);
                LDSM4(al[mf], ad + MMA_MATB);
            }
            #pragma unroll
            for (int np = 0; np < 4; np++) {
                uint32_t bd = baseB + (uint32_t)((wn * 64 + np * 16) * MMA_STR) + ks * 32 + boff;
                LDSM4(bh[np], bd);
                LDSM4(bl[np], bd + MMA_MATB);
            }
            #pragma unroll
            for (int mf = 0; mf < 2; mf++)
                #pragma unroll
                for (int np = 0; np < 4; np++)
                    #pragma unroll
                    for (int hh = 0; hh < 2; hh++) {
                        int nf = np * 2 + hh;
                        MMA_BF16(acc[mf][nf], ah[mf], bh[np][2 * hh], bh[np][2 * hh + 1]);
                        MMA_BF16(acc[mf][nf], al[mf], bh[np][2 * hh], bh[np][2 * hh + 1]);
                        MMA_BF16(acc[mf][nf], ah[mf], bl[np][2 * hh], bl[np][2 * hh + 1]);
                    }
        }
        if (kc + 1 < KCH) {
            cvt_store_chunk<KDIM, CH>(smem, (buf ^ 1) * MMA_BUFB, pfa, pfw, tid);
            __syncthreads();
            buf ^= 1;
        }
    }

    // ---- epilogue: write xp (fp16) + fused attention logits (fp32) ----
    #pragma unroll
    for (int mf = 0; mf < 2; mf++)
        #pragma unroll
        for (int r = 0; r < 2; r++) {
            int row_local = wm * 32 + mf * 16 + (lane >> 2) + r * 8;
            int m = brow + row_local;
            float als = 0.f, ald = 0.f;
            #pragma unroll
            for (int nf = 0; nf < 8; nf++) {
                float c0 = acc[mf][nf][r * 2 + 0], c1 = acc[mf][nf][r * 2 + 1];
                int j = wn * 64 + nf * 8 + (lane & 3) * 2;
                als += c0 * s_as[j] + c1 * s_as[j + 1];
                ald += c0 * s_ad[j] + c1 * s_ad[j + 1];
                if (m < M) {
                    int ncol = bcol + j;
                    int head = ncol / CH, c = ncol % CH;
                    *reinterpret_cast<__half2*>(xp + ((size_t)m * 2 + head) * CH + c) =
                        __floats2half2_rn(c0, c1);
                }
            }
            als += __shfl_xor_sync(0xffffffffu, als, 1);
            als += __shfl_xor_sync(0xffffffffu, als, 2);
            ald += __shfl_xor_sync(0xffffffffu, ald, 1);
            ald += __shfl_xor_sync(0xffffffffu, ald, 2);
            if ((lane & 3) == 0) {
                int sidx = (CH == 64 ? wn * 128 : 0) + row_local;
                atomicAdd(&s_als[sidx], als);
                atomicAdd(&s_ald[sidx], ald);
            }
        }
    __syncthreads();
    if (CH == 128) {
        if (tid < 128) {
            int m = brow + tid;
            if (m < M) {
                g_als[2 * m + blockIdx.x] = s_als[tid];
                g_ald[2 * m + blockIdx.x] = s_ald[tid];
            }
        }
    } else {
        int h = tid >> 7, t = tid & 127;
        int m = brow + t;
        if (m < M) {
            g_als[2 * m + h] = s_als[tid];
            g_ald[2 * m + h] = s_ald[tid];
        }
    }
}

// ---------------- warp-per-dst online-softmax aggregation --------------------
template <int C>
__device__ __forceinline__ void ld_row(const __half* row, float* v0, float* v1) {
    constexpr int V = C / 32;
    if constexpr (V == 4) {
        uint2 u0 = *reinterpret_cast<const uint2*>(row);
        uint2 u1 = *reinterpret_cast<const uint2*>(row + C);
        float2 a = __half22float2(*reinterpret_cast<__half2*>(&u0.x));
        float2 b = __half22float2(*reinterpret_cast<__half2*>(&u0.y));
        v0[0] = a.x; v0[1] = a.y; v0[2] = b.x; v0[3] = b.y;
        a = __half22float2(*reinterpret_cast<__half2*>(&u1.x));
        b = __half22float2(*reinterpret_cast<__half2*>(&u1.y));
        v1[0] = a.x; v1[1] = a.y; v1[2] = b.x; v1[3] = b.y;
    } else {
        float2 a = __half22float2(*reinterpret_cast<const __half2*>(row));
        float2 b = __half22float2(*reinterpret_cast<const __half2*>(row + C));
        v0[0] = a.x; v0[1] = a.y;
        v1[0] = b.x; v1[1] = b.y;
    }
}

// OUTH: write fp16 output (h1). CLS: fused classifier (fp32 out).
template <int C, bool RELU, bool CLS, bool OUTH>
__global__ void k_agg(const __half* __restrict__ xp, const float* __restrict__ bias,
                      void* __restrict__ outv, int keoff,
                      const float* __restrict__ Wc, const float* __restrict__ bc) {
    int warp = (blockIdx.x * blockDim.x + threadIdx.x) >> 5;
    int lane = threadIdx.x & 31;
    if (warp >= N_NODES) return;
    constexpr int V = C / 32;
    float acc0[V], acc1[V];
    #pragma unroll
    for (int j = 0; j < V; j++) { acc0[j] = 0.f; acc1[j] = 0.f; }
    float m0 = -1e30f, m1 = -1e30f, d0 = 0.f, d1 = 0.f;
    float ad0 = g_ald[2 * warp], ad1 = g_ald[2 * warp + 1];
    float ke0 = g_ke[keoff], ke1 = g_ke[keoff + 1];
    int p0 = g_rowptr[warp], p1 = g_rowptr[warp + 1];
    int c0 = lane * V;

    int p = p0;
    for (; p + 3 < p1; p += 4) {
        int2 ce[4];
        ce[0] = g_cole[p];     ce[1] = g_cole[p + 1];
        ce[2] = g_cole[p + 2]; ce[3] = g_cole[p + 3];
        float v0[4][V], v1[4][V];
        #pragma unroll
        for (int e = 0; e < 4; e++)
            ld_row<C>(xp + (size_t)ce[e].x * 2 * C + c0, v0[e], v1[e]);
        float a0[4], a1[4];
        #pragma unroll
        for (int e = 0; e < 4; e++) {
            float ea = __int_as_float(ce[e].y);
            float t0 = g_als[2 * ce[e].x]     + ad0 + ea * ke0;
            float t1 = g_als[2 * ce[e].x + 1] + ad1 + ea * ke1;
            a0[e] = t0 > 0.f ? t0 : 0.2f * t0;
            a1[e] = t1 > 0.f ? t1 : 0.2f * t1;
        }
        float nm0 = fmaxf(fmaxf(m0, fmaxf(a0[0], a0[1])), fmaxf(a0[2], a0[3]));
        float nm1 = fmaxf(fmaxf(m1, fmaxf(a1[0], a1[1])), fmaxf(a1[2], a1[3]));
        float sc0 = __expf(m0 - nm0), sc1 = __expf(m1 - nm1);
        float w0[4], w1[4];
        #pragma unroll
        for (int e = 0; e < 4; e++) {
            w0[e] = __expf(a0[e] - nm0);
            w1[e] = __expf(a1[e] - nm1);
        }
        d0 = d0 * sc0 + (w0[0] + w0[1]) + (w0[2] + w0[3]);
        d1 = d1 * sc1 + (w1[0] + w1[1]) + (w1[2] + w1[3]);
        m0 = nm0;  m1 = nm1;
        #pragma unroll
        for (int j = 0; j < V; j++) {
            float s0 = fmaf(w0[0], v0[0][j], w0[1] * v0[1][j]);
            s0 = fmaf(w0[2], v0[2][j], fmaf(w0[3], v0[3][j], s0));
            acc0[j] = fmaf(acc0[j], sc0, s0);
            float s1 = fmaf(w1[0], v1[0][j], w1[1] * v1[1][j]);
            s1 = fmaf(w1[2], v1[2][j], fmaf(w1[3], v1[3][j], s1));
            acc1[j] = fmaf(acc1[j], sc1, s1);
        }
    }
    for (; p < p1; p++) {
        int2 ce = g_cole[p];
        int s = ce.x;
        float ea = __int_as_float(ce.y);
        float v0[V], v1[V];
        ld_row<C>(xp + (size_t)s * 2 * C + c0, v0, v1);
        float a0 = g_als[2 * s]     + ad0 + ea * ke0;
        float a1 = g_als[2 * s + 1] + ad1 + ea * ke1;
        a0 = a0 > 0.f ? a0 : 0.2f * a0;
        a1 = a1 > 0.f ? a1 : 0.2f * a1;
        float nm0 = fmaxf(m0, a0), nm1 = fmaxf(m1, a1);
        float sc0 = __expf(m0 - nm0), sc1 = __expf(m1 - nm1);
        float w0  = __expf(a0 - nm0), w1  = __expf(a1 - nm1);
        d0 = d0 * sc0 + w0;  d1 = d1 * sc1 + w1;
        m0 = nm0;  m1 = nm1;
        #pragma unroll
        for (int j = 0; j < V; j++) {
            acc0[j] = fmaf(acc0[j], sc0, w0 * v0[j]);
            acc1[j] = fmaf(acc1[j], sc1, w1 * v1[j]);
        }
    }

    float r0 = 1.f / (d0 + 1e-16f), r1 = 1.f / (d1 + 1e-16f);
    float res[V];
    #pragma unroll
    for (int j = 0; j < V; j++) {
        float vv = 0.5f * (acc0[j] * r0 + acc1[j] * r1) + bias[c0 + j];
        if (RELU) vv = fmaxf(vv, 0.f);
        res[j] = vv;
    }
    if constexpr (!CLS) {
        if constexpr (OUTH) {
            __half* out = (__half*)outv;
            // V==4 path (layer 1): two half2 = 8B store
            __half2 h01 = __floats2half2_rn(res[0], res[1]);
            __half2 h23 = __floats2half2_rn(res[2], res[3]);
            uint2 u;
            u.x = *reinterpret_cast<uint32_t*>(&h01);
            u.y = *reinterpret_cast<uint32_t*>(&h23);
            *reinterpret_cast<uint2*>(&out[(size_t)warp * C + c0]) = u;
        } else {
            float* out = (float*)outv;
            if constexpr (V == 4)
                *reinterpret_cast<float4*>(&out[(size_t)warp * C + c0]) =
                    make_float4(res[0], res[1], res[2], res[3]);
            else
                *reinterpret_cast<float2*>(&out[(size_t)warp * C + c0]) =
                    make_float2(res[0], res[1]);
        }
    } else {
        float* out = (float*)outv;
        float part[NC];
        #pragma unroll
        for (int c = 0; c < NC; c++) {
            float s = 0.f;
            #pragma unroll
            for (int j = 0; j < V; j++)
                s = fmaf(res[j], __ldg(&Wc[(c0 + j) * NC + c]), s);
            part[c] = s;
        }
        #pragma unroll
        for (int off = 16; off; off >>= 1)
            #pragma unroll
            for (int c = 0; c < NC; c++)
                part[c] += __shfl_xor_sync(0xffffffffu, part[c], off);
        if (lane < NC)
            out[(size_t)warp * NC + lane] = part[lane] + __ldg(&bc[lane]);
    }
}

// ---------------- launch ------------------------------------------------------
static void* sym(const void* s) { void* p = nullptr; cudaGetSymbolAddress(&p, s); return p; }

extern "C" void kernel_launch(void* const* d_in, const int* in_sizes, int n_in,
                              void* d_out, int out_size) {
    const float* x    = (const float*)d_in[0];
    const int*   ei   = (const int*)  d_in[1];
    const float* ea   = (const float*)d_in[2];
    const int*   y    = (const int*)  d_in[4];
    const float* W1   = (const float*)d_in[5];
    const float* as1  = (const float*)d_in[6];
    const float* ad1  = (const float*)d_in[7];
    const float* We1  = (const float*)d_in[8];
    const float* ae1  = (const float*)d_in[9];
    const float* b1   = (const float*)d_in[10];
    const float* W2   = (const float*)d_in[11];
    const float* as2  = (const float*)d_in[12];
    const float* ad2  = (const float*)d_in[13];
    const float* We2  = (const float*)d_in[14];
    const float* ae2  = (const float*)d_in[15];
    const float* b2   = (const float*)d_in[16];
    const float* Wc   = (const float*)d_in[17];
    const float* bc   = (const float*)d_in[18];
    float* out = (float*)d_out;
    const int* src = ei;
    const int* dst = ei + N_EDGES;

    __half* xp1 = (__half*)sym(g_xp1);
    __half* h1  = (__half*)sym(g_h1);
    __half* xp2 = (__half*)sym(g_xp2);

    static cudaStream_t s2 = nullptr;
    static cudaEvent_t evFork = nullptr, evCSR = nullptr;
    if (!s2) {
        cudaStreamCreateWithFlags(&s2, cudaStreamNonBlocking);
        cudaEventCreateWithFlags(&evFork, cudaEventDisableTiming);
        cudaEventCreateWithFlags(&evCSR, cudaEventDisableTiming);
    }

    cudaFuncSetAttribute((const void*)k_mma<256, 128, float>,
                         cudaFuncAttributeMaxDynamicSharedMemorySize, MMA_SMEM);
    cudaFuncSetAttribute((const void*)k_mma<128, 64, __half>,
                         cudaFuncAttributeMaxDynamicSharedMemorySize, MMA_SMEM);

    const int MB = (N_NODES + 127) / 128;                // 391
    const int AGG_GRID = (N_NODES * 32 + 255) / 256;     // 6250

    float* outy = (out_size >= N_NODES * NC + N_NODES)
                      ? out + (size_t)N_NODES * NC : nullptr;

    // ---- fork: CSR chain on s2 concurrent with layer-1 GEMM ----
    cudaEventRecord(evFork, 0);
    cudaStreamWaitEvent(s2, evFork, 0);

    k_init<<<(N_NODES + 255) / 256, 256, 0, s2>>>();
    k_edge_pass1<<<512, 256, 0, s2>>>(src, dst, ea);
    k_scan1<<<NBLK_SCAN, 256, 0, s2>>>();
    k_scan2f<<<1, 256, 0, s2>>>(We1, ae1, We2, ae2);
    k_scan3<<<NBLK_SCAN, 256, 0, s2>>>();
    k_fill<<<1024, 256, 0, s2>>>(src, dst, ea, y, outy);
    cudaEventRecord(evCSR, s2);

    // main: layer-1 fused GEMM concurrent with CSR build
    k_mma<256, 128, float><<<dim3(2, MB), 256, MMA_SMEM>>>(x, W1, xp1, as1, ad1, N_NODES);
    cudaStreamWaitEvent(0, evCSR, 0);

    // layer 1 aggregation (writes h1 in fp16)
    k_agg<128, true, false, true><<<AGG_GRID, 256>>>(
        xp1, b1, (void*)h1, 0, nullptr, nullptr);

    // layer 2 (fp16 A input) + fused classifier
    k_mma<128, 64, __half><<<dim3(1, MB), 256, MMA_SMEM>>>(h1, W2, xp2, as2, ad2, N_NODES);
    k_agg<64, false, true, false><<<AGG_GRID, 256>>>(
        xp2, b2, (void*)out, 2, Wc, bc);
}

// round 16
// speedup vs baseline: 1.0571x; 1.0389x over previous
#include <cuda_runtime.h>
#include <cuda_bf16.h>
#include <cuda_fp16.h>
#include <stdint.h>

#define N_NODES 50000
#define N_EDGES 500000
#define NPG     6250
#define N_GRAPHS 8
#define TOT_EDGES (N_EDGES + N_NODES)
#define NC 10
#define NBLK_SCAN ((N_NODES + 255) / 256)   // 196

// ===================== mma.sync helpers (sm_80+ ISA) ========================
__device__ __forceinline__ uint32_t smem_to_u32(const void* p) {
    uint32_t a;
    asm("{ .reg .u64 t; cvta.to.shared.u64 t, %1; cvt.u32.u64 %0, t; }" : "=r"(a) : "l"(p));
    return a;
}
#define LDSM4(r, addr) \
    asm volatile("ldmatrix.sync.aligned.m8n8.x4.shared.b16 {%0,%1,%2,%3}, [%4];" \
        : "=r"((r)[0]), "=r"((r)[1]), "=r"((r)[2]), "=r"((r)[3]) : "r"(addr))
#define MMA_BF16(d, a, b0v, b1v) \
    asm volatile("mma.sync.aligned.m16n8k16.row.col.f32.bf16.bf16.f32 " \
        "{%0,%1,%2,%3}, {%4,%5,%6,%7}, {%8,%9}, {%0,%1,%2,%3};" \
        : "+f"((d)[0]), "+f"((d)[1]), "+f"((d)[2]), "+f"((d)[3]) \
        : "r"((a)[0]), "r"((a)[1]), "r"((a)[2]), "r"((a)[3]), "r"(b0v), "r"(b1v))

// ---------------- scratch (static __device__, no allocation) ----------------
__device__ __align__(16) __half g_xp1[(size_t)N_NODES * 256];
__device__ __align__(16) float  g_h1 [(size_t)N_NODES * 128];   // fp32 (reverted)
__device__ __align__(16) __half g_xp2[(size_t)N_NODES * 128];
__device__ __align__(8) float g_als[N_NODES * 2];
__device__ __align__(8) float g_ald[N_NODES * 2];
__device__ int   g_rowptr[N_NODES + 1];
__device__ int   g_cursor[N_NODES];
__device__ __align__(8) int2 g_cole[TOT_EDGES];   // {src, eav bits}
__device__ float g_gsum[N_GRAPHS];
__device__ int   g_gcnt[N_GRAPHS];
__device__ float g_mean[N_GRAPHS];
__device__ float g_ke[4];
__device__ int   g_bsum[NBLK_SCAN];

// ---------------- init ------------------------------------------------------
__global__ void k_init() {
    int i = blockIdx.x * blockDim.x + threadIdx.x;
    if (i < N_NODES) g_cursor[i] = 1;
    if (i < N_GRAPHS) { g_gsum[i] = 0.f; g_gcnt[i] = 0; }
}

// ---------------- edge pass: per-graph attr stats + in-degree hist ----------
__global__ void k_edge_pass1(const int* __restrict__ src, const int* __restrict__ dst,
                             const float* __restrict__ ea) {
    __shared__ float ss[N_GRAPHS];
    __shared__ int   sc[N_GRAPHS];
    if (threadIdx.x < N_GRAPHS) { ss[threadIdx.x] = 0.f; sc[threadIdx.x] = 0; }
    __syncthreads();
    for (int e = blockIdx.x * blockDim.x + threadIdx.x; e < N_EDGES;
         e += gridDim.x * blockDim.x) {
        int s = src[e];
        int d = dst[e];
        int g = s / NPG;
        atomicAdd(&ss[g], ea[e]);
        atomicAdd(&sc[g], 1);
        atomicAdd(&g_cursor[d], 1);
    }
    __syncthreads();
    if (threadIdx.x < N_GRAPHS) {
        atomicAdd(&g_gsum[threadIdx.x], ss[threadIdx.x]);
        atomicAdd(&g_gcnt[threadIdx.x], sc[threadIdx.x]);
    }
}

// ---------------- scan stage 1 -----------------------------------------------
__global__ void k_scan1() {
    int t = threadIdx.x;
    int i = blockIdx.x * 256 + t;
    int v = (i < N_NODES) ? g_cursor[i] : 0;
    int lane = t & 31, w = t >> 5;
    int x = v;
    #pragma unroll
    for (int o = 1; o < 32; o <<= 1) {
        int y = __shfl_up_sync(0xffffffffu, x, o);
        if (lane >= o) x += y;
    }
    __shared__ int ws[8];
    if (lane == 31) ws[w] = x;
    __syncthreads();
    if (t == 0) {
        int run = 0;
        #pragma unroll
        for (int j = 0; j < 8; j++) { int tmp = ws[j]; ws[j] = run; run += tmp; }
        g_bsum[blockIdx.x] = run;
    }
    __syncthreads();
    int excl = x - v + ws[w];
    if (i < N_NODES) g_rowptr[i] = excl;
}

// ---------------- scan stage 2 + finalize ------------------------------------
__global__ void k_scan2f(const float* __restrict__ We1, const float* __restrict__ ae1,
                         const float* __restrict__ We2, const float* __restrict__ ae2) {
    int t = threadIdx.x, w = t >> 5, lane = t & 31;
    {
        float v = 0.f;
        if (w == 0)      { for (int c = lane; c < 128; c += 32) v += We1[c]       * ae1[c]; }
        else if (w == 1) { for (int c = lane; c < 128; c += 32) v += We1[128 + c] * ae1[128 + c]; }
        else if (w == 2) { for (int c = lane; c <  64; c += 32) v += We2[c]       * ae2[c]; }
        else if (w == 3) { for (int c = lane; c <  64; c += 32) v += We2[64 + c]  * ae2[64 + c]; }
        #pragma unroll
        for (int off = 16; off; off >>= 1) v += __shfl_xor_sync(0xffffffffu, v, off);
        if (w < 4 && lane == 0) g_ke[w] = v;
        if (w == 4 && lane < N_GRAPHS)
            g_mean[lane] = g_gsum[lane] / (float)g_gcnt[lane];
    }
    int v = (t < NBLK_SCAN) ? g_bsum[t] : 0;
    int x = v;
    #pragma unroll
    for (int o = 1; o < 32; o <<= 1) {
        int y = __shfl_up_sync(0xffffffffu, x, o);
        if (lane >= o) x += y;
    }
    __shared__ int ws[8];
    if (lane == 31) ws[w] = x;
    __syncthreads();
    if (t == 0) {
        int run = 0;
        #pragma unroll
        for (int j = 0; j < 8; j++) { int tmp = ws[j]; ws[j] = run; run += tmp; }
        g_rowptr[N_NODES] = run;
    }
    __syncthreads();
    int excl = x - v + ws[w];
    if (t < NBLK_SCAN) g_bsum[t] = excl;
}

__global__ void k_scan3() {
    int i = blockIdx.x * 256 + threadIdx.x;
    if (i < N_NODES) {
        int r = g_rowptr[i] + g_bsum[blockIdx.x];
        g_rowptr[i] = r;
        g_cursor[i] = r;
    }
}

// ---------------- CSR fill (+ folded y cast) ----------------------------------
__global__ void k_fill(const int* __restrict__ src, const int* __restrict__ dst,
                       const float* __restrict__ ea,
                       const int* __restrict__ y, float* __restrict__ outy) {
    for (int i = blockIdx.x * blockDim.x + threadIdx.x; i < TOT_EDGES;
         i += gridDim.x * blockDim.x) {
        if (i < N_EDGES) {
            int d = dst[i];
            int p = atomicAdd(&g_cursor[d], 1);
            g_cole[p] = make_int2(src[i], __float_as_int(ea[i]));
        } else {
            int n = i - N_EDGES;
            int p = atomicAdd(&g_cursor[n], 1);
            g_cole[p] = make_int2(n, __float_as_int(g_mean[n / NPG]));
            if (outy) outy[n] = (float)y[n];
        }
    }
}

// ============ split-bf16 mma.sync GEMM + fused attention-logit epilogue ======
static constexpr int MMA_STR  = 80;
static constexpr int MMA_MATB = 128 * MMA_STR;
static constexpr int MMA_BUFB = 4 * MMA_MATB;
static constexpr int MMA_SMEM = 2 * MMA_BUFB + 512 + 512 + 1024 + 1024; // 84992

template <int KDIM, int CH>
__device__ __forceinline__ void cvt_store_chunk(char* smem, int bufoff,
                                                const float4* pfa, const float* pfw,
                                                int tid) {
    #pragma unroll
    for (int i = 0; i < 4; i++) {
        int idx = tid + i * 256;
        int row = idx >> 3, kq = idx & 7;
        float4 v = pfa[i];
        __nv_bfloat162 h0, h1, l0, l1;
        h0.x = __float2bfloat16(v.x); h0.y = __float2bfloat16(v.y);
        h1.x = __float2bfloat16(v.z); h1.y = __float2bfloat16(v.w);
        l0.x = __float2bfloat16(v.x - __bfloat162float(h0.x));
        l0.y = __float2bfloat16(v.y - __bfloat162float(h0.y));
        l1.x = __float2bfloat16(v.z - __bfloat162float(h1.x));
        l1.y = __float2bfloat16(v.w - __bfloat162float(h1.y));
        char* p = smem + bufoff + row * MMA_STR + kq * 8;
        *reinterpret_cast<__nv_bfloat162*>(p)     = h0;
        *reinterpret_cast<__nv_bfloat162*>(p + 4) = h1;
        *reinterpret_cast<__nv_bfloat162*>(p + MMA_MATB)     = l0;
        *reinterpret_cast<__nv_bfloat162*>(p + MMA_MATB + 4) = l1;
    }
    #pragma unroll
    for (int i = 0; i < 8; i++) {
        int idx = tid + i * 256;
        int k2 = idx >> 7, n = idx & 127;
        float w0 = pfw[2 * i], w1 = pfw[2 * i + 1];
        __nv_bfloat162 h, l;
        h.x = __float2bfloat16(w0); h.y = __float2bfloat16(w1);
        l.x = __float2bfloat16(w0 - __bfloat162float(h.x));
        l.y = __float2bfloat16(w1 - __bfloat162float(h.y));
        char* p = smem + bufoff + 2 * MMA_MATB + n * MMA_STR + k2 * 4;
        *reinterpret_cast<__nv_bfloat162*>(p)            = h;
        *reinterpret_cast<__nv_bfloat162*>(p + MMA_MATB) = l;
    }
}

// 2 CTAs/SM forced: regs capped at 128 (minor spills OK), smem 2x85KB fits 228KB.
template <int KDIM, int CH>
__global__ void __launch_bounds__(256, 2) k_mma(const float* __restrict__ A,
                                                const float* __restrict__ W,
                                                __half* __restrict__ xp,
                                                const float* __restrict__ asrc,
                                                const float* __restrict__ adst,
                                                int M) {
    extern __shared__ char smem[];
    constexpr int NW  = 2 * CH;
    constexpr int KCH = KDIM / 32;
    constexpr int SAS  = 2 * MMA_BUFB;
    constexpr int SAD  = SAS + 512;
    constexpr int SALS = SAD + 512;
    constexpr int SALD = SALS + 1024;

    const int tid = threadIdx.x;
    const int wid = tid >> 5, lane = tid & 31;
    const int wm = wid & 3, wn = wid >> 2;
    const int brow = blockIdx.y * 128;
    const int bcol = blockIdx.x * 128;
    const uint32_t sb = smem_to_u32(smem);

    float* s_as  = reinterpret_cast<float*>(smem + SAS);
    float* s_ad  = reinterpret_cast<float*>(smem + SAD);
    float* s_als = reinterpret_cast<float*>(smem + SALS);
    float* s_ald = reinterpret_cast<float*>(smem + SALD);
    if (tid < 128) { s_as[tid] = asrc[bcol + tid]; s_ad[tid] = adst[bcol + tid]; }
    s_als[tid] = 0.f;
    s_ald[tid] = 0.f;

    const uint32_t aoff = (uint32_t)((lane & 15) * MMA_STR + (lane >> 4) * 16);
    const uint32_t boff = (uint32_t)(((lane & 7) + ((lane >> 4) & 1) * 8) * MMA_STR
                                     + ((lane >> 3) & 1) * 16);

    float4 pfa[4];
    float  pfw[16];
    #pragma unroll
    for (int i = 0; i < 4; i++) {
        int idx = tid + i * 256;
        int row = idx >> 3, kq = idx & 7;
        int gr = brow + row;
        pfa[i] = (gr < M) ? *reinterpret_cast<const float4*>(A + (size_t)gr * KDIM + kq * 4)
                          : make_float4(0.f, 0.f, 0.f, 0.f);
    }
    #pragma unroll
    for (int i = 0; i < 8; i++) {
        int idx = tid + i * 256;
        int k = (idx >> 7) * 2, n = idx & 127;
        pfw[2 * i]     = W[(size_t)k * NW + bcol + n];
        pfw[2 * i + 1] = W[(size_t)(k + 1) * NW + bcol + n];
    }
    cvt_store_chunk<KDIM, CH>(smem, 0, pfa, pfw, tid);
    __syncthreads();

    float acc[2][8][4];
    #pragma unroll
    for (int a = 0; a < 2; a++)
        #pragma unroll
        for (int b = 0; b < 8; b++)
            #pragma unroll
            for (int c = 0; c < 4; c++) acc[a][b][c] = 0.f;

    int buf = 0;
    for (int kc = 0; kc < KCH; kc++) {
        if (kc + 1 < KCH) {
            const int kb = (kc + 1) * 32;
            #pragma unroll
            for (int i = 0; i < 4; i++) {
                int idx = tid + i * 256;
                int row = idx >> 3, kq = idx & 7;
                int gr = brow + row;
                pfa[i] = (gr < M)
                    ? *reinterpret_cast<const float4*>(A + (size_t)gr * KDIM + kb + kq * 4)
                    : make_float4(0.f, 0.f, 0.f, 0.f);
            }
            #pragma unroll
            for (int i = 0; i < 8; i++) {
                int idx = tid + i * 256;
                int k = kb + (idx >> 7) * 2, n = idx & 127;
                pfw[2 * i]     = W[(size_t)k * NW + bcol + n];
                pfw[2 * i + 1] = W[(size_t)(k + 1) * NW + bcol + n];
            }
        }
        const uint32_t baseA = sb + buf * MMA_BUFB;
        const uint32_t baseB = baseA + 2 * MMA_MATB;
        #pragma unroll
        for (int ks = 0; ks < 2; ks++) {
            uint32_t ah[2][4], al[2][4], bh[4][4], bl[4][4];
            #pragma unroll
            for (int mf = 0; mf < 2; mf++) {
                uint32_t ad = baseA + (uint32_t)((wm * 32 + mf * 16) * MMA_STR) + ks * 32 + aoff;
                LDSM4(ah[mf], ad);
                LDSM4(al[mf], ad + MMA_MATB);
            }
            #pragma unroll
            for (int np = 0; np < 4; np++) {
                uint32_t bd = baseB + (uint32_t)((wn * 64 + np * 16) * MMA_STR) + ks * 32 + boff;
                LDSM4(bh[np], bd);
                LDSM4(bl[np], bd + MMA_MATB);
            }
            #pragma unroll
            for (int mf = 0; mf < 2; mf++)
                #pragma unroll
                for (int np = 0; np < 4; np++)
                    #pragma unroll
                    for (int hh = 0; hh < 2; hh++) {
                        int nf = np * 2 + hh;
                        MMA_BF16(acc[mf][nf], ah[mf], bh[np][2 * hh], bh[np][2 * hh + 1]);
                        MMA_BF16(acc[mf][nf], al[mf], bh[np][2 * hh], bh[np][2 * hh + 1]);
                        MMA_BF16(acc[mf][nf], ah[mf], bl[np][2 * hh], bl[np][2 * hh + 1]);
                    }
        }
        if (kc + 1 < KCH) {
            cvt_store_chunk<KDIM, CH>(smem, (buf ^ 1) * MMA_BUFB, pfa, pfw, tid);
            __syncthreads();
            buf ^= 1;
        }
    }

    // ---- epilogue: write xp (fp16) + fused attention logits (fp32) ----
    #pragma unroll
    for (int mf = 0; mf < 2; mf++)
        #pragma unroll
        for (int r = 0; r < 2; r++) {
            int row_local = wm * 32 + mf * 16 + (lane >> 2) + r * 8;
            int m = brow + row_local;
            float als = 0.f, ald = 0.f;
            #pragma unroll
            for (int nf = 0; nf < 8; nf++) {
                float c0 = acc[mf][nf][r * 2 + 0], c1 = acc[mf][nf][r * 2 + 1];
                int j = wn * 64 + nf * 8 + (lane & 3) * 2;
                als += c0 * s_as[j] + c1 * s_as[j + 1];
                ald += c0 * s_ad[j] + c1 * s_ad[j + 1];
                if (m < M) {
                    int ncol = bcol + j;
                    int head = ncol / CH, c = ncol % CH;
                    *reinterpret_cast<__half2*>(xp + ((size_t)m * 2 + head) * CH + c) =
                        __floats2half2_rn(c0, c1);
                }
            }
            als += __shfl_xor_sync(0xffffffffu, als, 1);
            als += __shfl_xor_sync(0xffffffffu, als, 2);
            ald += __shfl_xor_sync(0xffffffffu, ald, 1);
            ald += __shfl_xor_sync(0xffffffffu, ald, 2);
            if ((lane & 3) == 0) {
                int sidx = (CH == 64 ? wn * 128 : 0) + row_local;
                atomicAdd(&s_als[sidx], als);
                atomicAdd(&s_ald[sidx], ald);
            }
        }
    __syncthreads();
    if (CH == 128) {
        if (tid < 128) {
            int m = brow + tid;
            if (m < M) {
                g_als[2 * m + blockIdx.x] = s_als[tid];
                g_ald[2 * m + blockIdx.x] = s_ald[tid];
            }
        }
    } else {
        int h = tid >> 7, t = tid & 127;
        int m = brow + t;
        if (m < M) {
            g_als[2 * m + h] = s_als[tid];
            g_ald[2 * m + h] = s_ald[tid];
        }
    }
}

// ---------------- warp-per-dst online-softmax aggregation (R13 layout) -------
template <int C>
__device__ __forceinline__ void ld_row(const __half* row, float* v0, float* v1) {
    constexpr int V = C / 32;
    if constexpr (V == 4) {
        uint2 u0 = *reinterpret_cast<const uint2*>(row);
        uint2 u1 = *reinterpret_cast<const uint2*>(row + C);
        float2 a = __half22float2(*reinterpret_cast<__half2*>(&u0.x));
        float2 b = __half22float2(*reinterpret_cast<__half2*>(&u0.y));
        v0[0] = a.x; v0[1] = a.y; v0[2] = b.x; v0[3] = b.y;
        a = __half22float2(*reinterpret_cast<__half2*>(&u1.x));
        b = __half22float2(*reinterpret_cast<__half2*>(&u1.y));
        v1[0] = a.x; v1[1] = a.y; v1[2] = b.x; v1[3] = b.y;
    } else {
        float2 a = __half22float2(*reinterpret_cast<const __half2*>(row));
        float2 b = __half22float2(*reinterpret_cast<const __half2*>(row + C));
        v0[0] = a.x; v0[1] = a.y;
        v1[0] = b.x; v1[1] = b.y;
    }
}

template <int C, bool RELU, bool CLS>
__global__ void k_agg(const __half* __restrict__ xp, const float* __restrict__ bias,
                      float* __restrict__ out, int keoff,
                      const float* __restrict__ Wc, const float* __restrict__ bc) {
    int warp = (blockIdx.x * blockDim.x + threadIdx.x) >> 5;
    int lane = threadIdx.x & 31;
    if (warp >= N_NODES) return;
    constexpr int V = C / 32;
    float acc0[V], acc1[V];
    #pragma unroll
    for (int j = 0; j < V; j++) { acc0[j] = 0.f; acc1[j] = 0.f; }
    float m0 = -1e30f, m1 = -1e30f, d0 = 0.f, d1 = 0.f;
    float ad0 = g_ald[2 * warp], ad1 = g_ald[2 * warp + 1];
    float ke0 = g_ke[keoff], ke1 = g_ke[keoff + 1];
    int p0 = g_rowptr[warp], p1 = g_rowptr[warp + 1];
    int c0 = lane * V;

    int p = p0;
    for (; p + 3 < p1; p += 4) {
        int2 ce[4];
        ce[0] = g_cole[p];     ce[1] = g_cole[p + 1];
        ce[2] = g_cole[p + 2]; ce[3] = g_cole[p + 3];
        float v0[4][V], v1[4][V];
        #pragma unroll
        for (int e = 0; e < 4; e++)
            ld_row<C>(xp + (size_t)ce[e].x * 2 * C + c0, v0[e], v1[e]);
        float a0[4], a1[4];
        #pragma unroll
        for (int e = 0; e < 4; e++) {
            float ea = __int_as_float(ce[e].y);
            float t0 = g_als[2 * ce[e].x]     + ad0 + ea * ke0;
            float t1 = g_als[2 * ce[e].x + 1] + ad1 + ea * ke1;
            a0[e] = t0 > 0.f ? t0 : 0.2f * t0;
            a1[e] = t1 > 0.f ? t1 : 0.2f * t1;
        }
        float nm0 = fmaxf(fmaxf(m0, fmaxf(a0[0], a0[1])), fmaxf(a0[2], a0[3]));
        float nm1 = fmaxf(fmaxf(m1, fmaxf(a1[0], a1[1])), fmaxf(a1[2], a1[3]));
        float sc0 = __expf(m0 - nm0), sc1 = __expf(m1 - nm1);
        float w0[4], w1[4];
        #pragma unroll
        for (int e = 0; e < 4; e++) {
            w0[e] = __expf(a0[e] - nm0);
            w1[e] = __expf(a1[e] - nm1);
        }
        d0 = d0 * sc0 + (w0[0] + w0[1]) + (w0[2] + w0[3]);
        d1 = d1 * sc1 + (w1[0] + w1[1]) + (w1[2] + w1[3]);
        m0 = nm0;  m1 = nm1;
        #pragma unroll
        for (int j = 0; j < V; j++) {
            float s0 = fmaf(w0[0], v0[0][j], w0[1] * v0[1][j]);
            s0 = fmaf(w0[2], v0[2][j], fmaf(w0[3], v0[3][j], s0));
            acc0[j] = fmaf(acc0[j], sc0, s0);
            float s1 = fmaf(w1[0], v1[0][j], w1[1] * v1[1][j]);
            s1 = fmaf(w1[2], v1[2][j], fmaf(w1[3], v1[3][j], s1));
            acc1[j] = fmaf(acc1[j], sc1, s1);
        }
    }
    for (; p < p1; p++) {
        int2 ce = g_cole[p];
        int s = ce.x;
        float ea = __int_as_float(ce.y);
        float v0[V], v1[V];
        ld_row<C>(xp + (size_t)s * 2 * C + c0, v0, v1);
        float a0 = g_als[2 * s]     + ad0 + ea * ke0;
        float a1 = g_als[2 * s + 1] + ad1 + ea * ke1;
        a0 = a0 > 0.f ? a0 : 0.2f * a0;
        a1 = a1 > 0.f ? a1 : 0.2f * a1;
        float nm0 = fmaxf(m0, a0), nm1 = fmaxf(m1, a1);
        float sc0 = __expf(m0 - nm0), sc1 = __expf(m1 - nm1);
        float w0  = __expf(a0 - nm0), w1  = __expf(a1 - nm1);
        d0 = d0 * sc0 + w0;  d1 = d1 * sc1 + w1;
        m0 = nm0;  m1 = nm1;
        #pragma unroll
        for (int j = 0; j < V; j++) {
            acc0[j] = fmaf(acc0[j], sc0, w0 * v0[j]);
            acc1[j] = fmaf(acc1[j], sc1, w1 * v1[j]);
        }
    }

    float r0 = 1.f / (d0 + 1e-16f), r1 = 1.f / (d1 + 1e-16f);
    float res[V];
    #pragma unroll
    for (int j = 0; j < V; j++) {
        float vv = 0.5f * (acc0[j] * r0 + acc1[j] * r1) + bias[c0 + j];
        if (RELU) vv = fmaxf(vv, 0.f);
        res[j] = vv;
    }
    if constexpr (!CLS) {
        if constexpr (V == 4)
            *reinterpret_cast<float4*>(&out[(size_t)warp * C + c0]) =
                make_float4(res[0], res[1], res[2], res[3]);
        else
            *reinterpret_cast<float2*>(&out[(size_t)warp * C + c0]) =
                make_float2(res[0], res[1]);
    } else {
        float part[NC];
        #pragma unroll
        for (int c = 0; c < NC; c++) {
            float s = 0.f;
            #pragma unroll
            for (int j = 0; j < V; j++)
                s = fmaf(res[j], __ldg(&Wc[(c0 + j) * NC + c]), s);
            part[c] = s;
        }
        #pragma unroll
        for (int off = 16; off; off >>= 1)
            #pragma unroll
            for (int c = 0; c < NC; c++)
                part[c] += __shfl_xor_sync(0xffffffffu, part[c], off);
        if (lane < NC)
            out[(size_t)warp * NC + lane] = part[lane] + __ldg(&bc[lane]);
    }
}

// ---------------- launch ------------------------------------------------------
static void* sym(const void* s) { void* p = nullptr; cudaGetSymbolAddress(&p, s); return p; }

extern "C" void kernel_launch(void* const* d_in, const int* in_sizes, int n_in,
                              void* d_out, int out_size) {
    const float* x    = (const float*)d_in[0];
    const int*   ei   = (const int*)  d_in[1];
    const float* ea   = (const float*)d_in[2];
    const int*   y    = (const int*)  d_in[4];
    const float* W1   = (const float*)d_in[5];
    const float* as1  = (const float*)d_in[6];
    const float* ad1  = (const float*)d_in[7];
    const float* We1  = (const float*)d_in[8];
    const float* ae1  = (const float*)d_in[9];
    const float* b1   = (const float*)d_in[10];
    const float* W2   = (const float*)d_in[11];
    const float* as2  = (const float*)d_in[12];
    const float* ad2  = (const float*)d_in[13];
    const float* We2  = (const float*)d_in[14];
    const float* ae2  = (const float*)d_in[15];
    const float* b2   = (const float*)d_in[16];
    const float* Wc   = (const float*)d_in[17];
    const float* bc   = (const float*)d_in[18];
    float* out = (float*)d_out;
    const int* src = ei;
    const int* dst = ei + N_EDGES;

    __half* xp1 = (__half*)sym(g_xp1);
    float*  h1  = (float*) sym(g_h1);
    __half* xp2 = (__half*)sym(g_xp2);

    static cudaStream_t s2 = nullptr;
    static cudaEvent_t evFork = nullptr, evCSR = nullptr;
    if (!s2) {
        cudaStreamCreateWithFlags(&s2, cudaStreamNonBlocking);
        cudaEventCreateWithFlags(&evFork, cudaEventDisableTiming);
        cudaEventCreateWithFlags(&evCSR, cudaEventDisableTiming);
    }

    cudaFuncSetAttribute(k_mma<256, 128>,
                         cudaFuncAttributeMaxDynamicSharedMemorySize, MMA_SMEM);
    cudaFuncSetAttribute(k_mma<128, 64>,
                         cudaFuncAttributeMaxDynamicSharedMemorySize, MMA_SMEM);

    const int MB = (N_NODES + 127) / 128;                // 391
    const int AGG_GRID = (N_NODES * 32 + 255) / 256;     // 6250

    float* outy = (out_size >= N_NODES * NC + N_NODES)
                      ? out + (size_t)N_NODES * NC : nullptr;

    // ---- fork: CSR chain on s2 concurrent with layer-1 GEMM ----
    cudaEventRecord(evFork, 0);
    cudaStreamWaitEvent(s2, evFork, 0);

    k_init<<<(N_NODES + 255) / 256, 256, 0, s2>>>();
    k_edge_pass1<<<512, 256, 0, s2>>>(src, dst, ea);
    k_scan1<<<NBLK_SCAN, 256, 0, s2>>>();
    k_scan2f<<<1, 256, 0, s2>>>(We1, ae1, We2, ae2);
    k_scan3<<<NBLK_SCAN, 256, 0, s2>>>();
    k_fill<<<1024, 256, 0, s2>>>(src, dst, ea, y, outy);
    cudaEventRecord(evCSR, s2);

    // main: layer-1 fused GEMM concurrent with CSR build
    k_mma<256, 128><<<dim3(2, MB), 256, MMA_SMEM>>>(x, W1, xp1, as1, ad1, N_NODES);
    cudaStreamWaitEvent(0, evCSR, 0);

    // layer 1 aggregation
    k_agg<128, true, false><<<AGG_GRID, 256>>>(xp1, b1, h1, 0, nullptr, nullptr);

    // layer 2 + fused classifier
    k_mma<128, 64><<<dim3(1, MB), 256, MMA_SMEM>>>(h1, W2, xp2, as2, ad2, N_NODES);
    k_agg<64, false, true><<<AGG_GRID, 256>>>(xp2, b2, out, 2, Wc, bc);
}